// round 8
// baseline (speedup 1.0000x reference)
#include <cuda_runtime.h>

#define N_SPH 128
#define CAP   256          // per-block compaction capacity (overflow -> slow path)
typedef unsigned long long u64;

// -ln(1e-6)/32 : exact output when s clamps at 1e-6
#define FASTVAL 0.4317347049363836f

// ---- packed f32x2 helpers (sm_100+) ----
__device__ __forceinline__ u64 pk2(float lo, float hi) {
    u64 r; asm("mov.b64 %0, {%1, %2};" : "=l"(r) : "f"(lo), "f"(hi)); return r;
}
__device__ __forceinline__ float2 up2(u64 v) {
    float2 f; asm("mov.b64 {%0, %1}, %2;" : "=f"(f.x), "=f"(f.y) : "l"(v)); return f;
}
__device__ __forceinline__ u64 f2fma(u64 a, u64 b, u64 c) {
    u64 d; asm("fma.rn.f32x2 %0, %1, %2, %3;" : "=l"(d) : "l"(a), "l"(b), "l"(c)); return d;
}
__device__ __forceinline__ u64 f2mul(u64 a, u64 b) {
    u64 d; asm("mul.rn.f32x2 %0, %1, %2;" : "=l"(d) : "l"(a), "l"(b)); return d;
}
__device__ __forceinline__ float sqrt_ap(float x) {
    float r; asm("sqrt.approx.f32 %0, %1;" : "=f"(r) : "f"(x)); return r;
}
__device__ __forceinline__ float ex2_ap(float x) {
    float r; asm("ex2.approx.f32 %0, %1;" : "=f"(r) : "f"(x)); return r;
}
__device__ __forceinline__ float lg2_ap(float x) {
    float r; asm("lg2.approx.f32 %0, %1;" : "=f"(r) : "f"(x)); return r;
}

__global__ void __launch_bounds__(256, 5) smoothed_fused(
    const float* __restrict__ p,
    const float* __restrict__ centers,
    const float* __restrict__ radii,
    const float* __restrict__ tfs,
    float* __restrict__ out, int npts) {

    // consts: per sphere 28 floats (each value duplicated into f32x2 lanes)
    __shared__ __align__(16) float  shc[N_SPH * 28];        // 14336 B
    __shared__ __align__(16) float4 sbuf[CAP];              //  4096 B
    __shared__ float  spart[16 * 257];                      // 16448 B (257 kills conflicts)
    __shared__ int s_thr2_bits;
    __shared__ int s_count;

    const int tid = threadIdx.x;
    if (tid == 0) { s_thr2_bits = 0; s_count = 0; }

    // ---- prefetch this thread's 4 points ----
    int t = blockIdx.x * 256 + tid;
    int base = t * 4;
    float4 va, vb, vc;
    bool inb = base < npts;
    if (inb) {
        const float4* p4 = reinterpret_cast<const float4*>(p);
        int f = t * 3;
        va = p4[f]; vb = p4[f + 1]; vc = p4[f + 2];
    }
    __syncthreads();

    // ---- phase A: threads 0..127 build sphere consts + radial threshold ----
    if (tid < N_SPH) {
        int i = tid;
        float T[3][3];
        #pragma unroll
        for (int r = 0; r < 3; ++r)
            #pragma unroll
            for (int c = 0; c < 3; ++c)
                T[r][c] = tfs[i * 9 + r * 3 + c] + ((r == c) ? 1.0f : 0.0f);
        float cx = centers[i * 3], cy = centers[i * 3 + 1], cz = centers[i * 3 + 2];
        float rad = radii[i];

        float* s = shc + i * 28;
        #pragma unroll
        for (int r = 0; r < 3; ++r) {
            float cs3[4] = {T[r][0], T[r][1], T[r][2],
                            (r == 0 ? -cx : (r == 1 ? -cy : -cz))};
            #pragma unroll
            for (int c = 0; c < 4; ++c) {
                s[(r * 4 + c) * 2]     = cs3[c];
                s[(r * 4 + c) * 2 + 1] = cs3[c];
            }
        }
        float b = 46.16624130844683f * rad;  // 32*log2(e)*r
        s[24] = b; s[25] = b; s[26] = 0.f; s[27] = 0.f;

        // sigma_min lower bound: lambda_min(T^T T) >= q - 2*sqrt(p2/6)
        float M00 = 0, M11 = 0, M22 = 0, M01 = 0, M02 = 0, M12 = 0;
        #pragma unroll
        for (int k = 0; k < 3; ++k) {
            float t0 = T[k][0], t1 = T[k][1], t2 = T[k][2];
            M00 = fmaf(t0, t0, M00); M11 = fmaf(t1, t1, M11); M22 = fmaf(t2, t2, M22);
            M01 = fmaf(t0, t1, M01); M02 = fmaf(t0, t2, M02); M12 = fmaf(t1, t2, M12);
        }
        float q  = (M00 + M11 + M22) * (1.0f / 3.0f);
        float a0 = M00 - q, a1 = M11 - q, a2 = M22 - q;
        float p2 = a0 * a0 + a1 * a1 + a2 * a2
                 + 2.0f * (M01 * M01 + M02 * M02 + M12 * M12);
        float lmin = q - 2.001f * sqrtf(fmaxf(p2, 0.0f) * (1.0f / 6.0f)) - 1e-6f;
        float sig  = sqrtf(fmaxf(lmin, 0.0f)) * 0.999f;
        float cn   = sqrtf(cx * cx + cy * cy + cz * cz) * 1.0001f + 1e-7f;
        float num  = 0.601f + cn + rad;   // 0.601 > (ln128+ln1e6)/32 = 0.5834
        float thr2 = 1e30f;               // sig~0 => no culling (still correct)
        if (sig > 1e-6f) {
            float thr = num / sig;
            thr2 = thr * thr * 1.002f;
        }
        atomicMax(&s_thr2_bits, __float_as_int(thr2));
    }
    __syncthreads();
    float R2 = __int_as_float(s_thr2_bits);

    // ---- phase B: classify, compact into shared (cap CAP), overflow slow path ----
    float x[4], y[4], z[4];
    bool nearf[4] = {false, false, false, false};
    int cnt = 0;
    if (inb) {
        x[0] = va.x; y[0] = va.y; z[0] = va.z;
        x[1] = va.w; y[1] = vb.x; z[1] = vb.y;
        x[2] = vb.z; y[2] = vb.w; z[2] = vc.x;
        x[3] = vc.y; y[3] = vc.z; z[3] = vc.w;
        #pragma unroll
        for (int k = 0; k < 4; ++k) {
            float n2 = fmaf(x[k], x[k], fmaf(y[k], y[k], z[k] * z[k]));
            nearf[k] = n2 < R2;
            if (!nearf[k]) out[base + k] = FASTVAL;
            cnt += nearf[k] ? 1 : 0;
        }
    }
    unsigned mask = 0xffffffffu;
    int lane = tid & 31;
    int incl = cnt;
    #pragma unroll
    for (int d = 1; d < 32; d <<= 1) {
        int v = __shfl_up_sync(mask, incl, d);
        if (lane >= d) incl += v;
    }
    int total = __shfl_sync(mask, incl, 31);
    int wbase = 0;
    if (lane == 0) wbase = (total > 0) ? atomicAdd(&s_count, total) : 0;
    wbase = __shfl_sync(mask, wbase, 0);
    int off = wbase + incl - cnt;
    #pragma unroll
    for (int k = 0; k < 4; ++k) {
        if (nearf[k]) {
            if (off < CAP) {
                sbuf[off] = make_float4(x[k], y[k], z[k], __int_as_float(base + k));
            } else {
                // overflow slow path: full scalar loop (correct, rare)
                float ssum = 0.f;
                for (int i = 0; i < N_SPH; ++i) {
                    const float* s = shc + i * 28;
                    float qx = fmaf(s[0], x[k], fmaf(s[2], y[k], fmaf(s[4],  z[k], s[6])));
                    float qy = fmaf(s[8], x[k], fmaf(s[10], y[k], fmaf(s[12], z[k], s[14])));
                    float qz = fmaf(s[16], x[k], fmaf(s[18], y[k], fmaf(s[20], z[k], s[22])));
                    float d2 = fmaf(qx, qx, fmaf(qy, qy, qz * qz));
                    ssum += ex2_ap(fmaf(sqrt_ap(d2), -46.16624130844683f, s[24]));
                }
                out[base + k] = lg2_ap(fmaxf(ssum, 1e-6f)) * -0.021660849392498290f;
            }
            off++;
        }
    }
    __syncthreads();

    // ---- phase C: unit = (pair j, group g of 8 spheres); j=u>>4, g=u&15 ----
    int count = min(s_count, CAP);
    int pairs = (count + 1) >> 1;
    int total_u = pairs << 4;

    for (int u = tid; u < total_u; u += 256) {
        int j = u >> 4;
        int g = u & 15;

        int ia = 2 * j;
        int ib = min(2 * j + 1, count - 1);
        float4 A = sbuf[ia];
        float4 B = sbuf[ib];

        u64 X = pk2(A.x, B.x), Y = pk2(A.y, B.y), Z = pk2(A.z, B.z);
        float s0 = 0.f, s1 = 0.f;

        const float* cb = shc + g * (8 * 28);
        #pragma unroll 4
        for (int sp = 0; sp < 8; ++sp) {
            const ulonglong2* C = reinterpret_cast<const ulonglong2*>(cb + sp * 28);
            ulonglong2 m0 = C[0];  // (t00, t01)
            ulonglong2 m1 = C[1];  // (t02, -cx)
            ulonglong2 m2 = C[2];  // (t10, t11)
            ulonglong2 m3 = C[3];  // (t12, -cy)
            ulonglong2 m4 = C[4];  // (t20, t21)
            ulonglong2 m5 = C[5];  // (t22, -cz)
            u64 bb = reinterpret_cast<const u64*>(C)[12];

            u64 qx = f2fma(m0.x, X, f2fma(m0.y, Y, f2fma(m1.x, Z, m1.y)));
            u64 qy = f2fma(m2.x, X, f2fma(m2.y, Y, f2fma(m3.x, Z, m3.y)));
            u64 qz = f2fma(m4.x, X, f2fma(m4.y, Y, f2fma(m5.x, Z, m5.y)));
            u64 d2 = f2fma(qx, qx, f2fma(qy, qy, f2mul(qz, qz)));

            float2 d  = up2(d2);
            float2 bs = up2(bb);
            s0 += ex2_ap(fmaf(sqrt_ap(d.x), -46.16624130844683f, bs.x));
            s1 += ex2_ap(fmaf(sqrt_ap(d.y), -46.16624130844683f, bs.y));
        }

        spart[g * 257 + ia] = s0;
        if (2 * j + 1 < count) spart[g * 257 + ib] = s1;
    }
    __syncthreads();

    // ---- phase D: fixed-order combine of 16 group partials per point ----
    const float NEG_LN2_32 = -0.021660849392498290f;
    for (int pt = tid; pt < count; pt += 256) {
        float acc[16];
        #pragma unroll
        for (int g = 0; g < 16; ++g) acc[g] = spart[g * 257 + pt];
        float s = (((acc[0] + acc[1]) + (acc[2] + acc[3]))
                 + ((acc[4] + acc[5]) + (acc[6] + acc[7])))
                + (((acc[8] + acc[9]) + (acc[10] + acc[11]))
                 + ((acc[12] + acc[13]) + (acc[14] + acc[15])));
        out[__float_as_int(sbuf[pt].w)] = lg2_ap(fmaxf(s, 1e-6f)) * NEG_LN2_32;
    }
}

extern "C" void kernel_launch(void* const* d_in, const int* in_sizes, int n_in,
                              void* d_out, int out_size) {
    const float* p       = (const float*)d_in[0];
    const float* centers = (const float*)d_in[1];
    const float* radii   = (const float*)d_in[2];
    const float* tfs     = (const float*)d_in[3];
    float* out = (float*)d_out;

    int npts = in_sizes[0] / 3;
    int blocks = (npts + 1023) / 1024;  // 256 threads x 4 points
    smoothed_fused<<<blocks, 256>>>(p, centers, radii, tfs, out, npts);
}

// round 9
// speedup vs baseline: 8.6077x; 8.6077x over previous
#include <cuda_runtime.h>

#define N_SPH 128
#define CAP   256          // per-block compaction capacity (overflow -> slow path)
typedef unsigned long long u64;

// -ln(1e-6)/32 : exact output when s clamps at 1e-6
#define FASTVAL 0.4317347049363836f

// ---- packed f32x2 helpers (sm_100+) ----
__device__ __forceinline__ u64 pk2(float lo, float hi) {
    u64 r; asm("mov.b64 %0, {%1, %2};" : "=l"(r) : "f"(lo), "f"(hi)); return r;
}
__device__ __forceinline__ float2 up2(u64 v) {
    float2 f; asm("mov.b64 {%0, %1}, %2;" : "=f"(f.x), "=f"(f.y) : "l"(v)); return f;
}
__device__ __forceinline__ u64 f2fma(u64 a, u64 b, u64 c) {
    u64 d; asm("fma.rn.f32x2 %0, %1, %2, %3;" : "=l"(d) : "l"(a), "l"(b), "l"(c)); return d;
}
__device__ __forceinline__ u64 f2mul(u64 a, u64 b) {
    u64 d; asm("mul.rn.f32x2 %0, %1, %2;" : "=l"(d) : "l"(a), "l"(b)); return d;
}
__device__ __forceinline__ float sqrt_ap(float x) {
    float r; asm("sqrt.approx.f32 %0, %1;" : "=f"(r) : "f"(x)); return r;
}
__device__ __forceinline__ float ex2_ap(float x) {
    float r; asm("ex2.approx.f32 %0, %1;" : "=f"(r) : "f"(x)); return r;
}
__device__ __forceinline__ float lg2_ap(float x) {
    float r; asm("lg2.approx.f32 %0, %1;" : "=f"(r) : "f"(x)); return r;
}

__global__ void __launch_bounds__(256, 5) smoothed_fused(
    const float* __restrict__ p,
    const float* __restrict__ centers,
    const float* __restrict__ radii,
    const float* __restrict__ tfs,
    float* __restrict__ out, int npts) {

    // consts: per sphere 28 floats (each value duplicated into f32x2 lanes)
    __shared__ __align__(16) float  shc[N_SPH * 28];        // 14336 B
    __shared__ __align__(16) float4 sbuf[CAP];              //  4096 B
    __shared__ float  spart[8 * 257];                       //  8224 B (257: conflict-free)
    __shared__ int s_thr2_bits;
    __shared__ int s_count;

    const int tid = threadIdx.x;
    if (tid == 0) { s_thr2_bits = 0; s_count = 0; }

    // ---- prefetch this thread's 4 points ----
    int t = blockIdx.x * 256 + tid;
    int base = t * 4;
    float4 va, vb, vc;
    bool inb = base < npts;
    if (inb) {
        const float4* p4 = reinterpret_cast<const float4*>(p);
        int f = t * 3;
        va = p4[f]; vb = p4[f + 1]; vc = p4[f + 2];
    }
    __syncthreads();

    // ---- phase A: threads 0..127 build sphere consts + radial threshold ----
    if (tid < N_SPH) {
        int i = tid;
        float T[3][3];
        #pragma unroll
        for (int r = 0; r < 3; ++r)
            #pragma unroll
            for (int c = 0; c < 3; ++c)
                T[r][c] = tfs[i * 9 + r * 3 + c] + ((r == c) ? 1.0f : 0.0f);
        float cx = centers[i * 3], cy = centers[i * 3 + 1], cz = centers[i * 3 + 2];
        float rad = radii[i];

        float* s = shc + i * 28;
        #pragma unroll
        for (int r = 0; r < 3; ++r) {
            float cs3[4] = {T[r][0], T[r][1], T[r][2],
                            (r == 0 ? -cx : (r == 1 ? -cy : -cz))};
            #pragma unroll
            for (int c = 0; c < 4; ++c) {
                s[(r * 4 + c) * 2]     = cs3[c];
                s[(r * 4 + c) * 2 + 1] = cs3[c];
            }
        }
        float b = 46.16624130844683f * rad;  // 32*log2(e)*r
        s[24] = b; s[25] = b; s[26] = 0.f; s[27] = 0.f;

        // sigma_min lower bound: lambda_min(T^T T) >= q - 2*sqrt(p2/6)
        float M00 = 0, M11 = 0, M22 = 0, M01 = 0, M02 = 0, M12 = 0;
        #pragma unroll
        for (int k = 0; k < 3; ++k) {
            float t0 = T[k][0], t1 = T[k][1], t2 = T[k][2];
            M00 = fmaf(t0, t0, M00); M11 = fmaf(t1, t1, M11); M22 = fmaf(t2, t2, M22);
            M01 = fmaf(t0, t1, M01); M02 = fmaf(t0, t2, M02); M12 = fmaf(t1, t2, M12);
        }
        float q  = (M00 + M11 + M22) * (1.0f / 3.0f);
        float a0 = M00 - q, a1 = M11 - q, a2 = M22 - q;
        float p2 = a0 * a0 + a1 * a1 + a2 * a2
                 + 2.0f * (M01 * M01 + M02 * M02 + M12 * M12);
        float lmin = q - 2.001f * sqrtf(fmaxf(p2, 0.0f) * (1.0f / 6.0f)) - 1e-6f;
        float sig  = sqrtf(fmaxf(lmin, 0.0f)) * 0.999f;
        float cn   = sqrtf(cx * cx + cy * cy + cz * cz) * 1.0001f + 1e-7f;
        float num  = 0.601f + cn + rad;   // 0.601 > (ln128+ln1e6)/32 = 0.5834
        float thr2 = 1e30f;               // sig~0 => no culling (still correct)
        if (sig > 1e-6f) {
            float thr = num / sig;
            thr2 = thr * thr * 1.002f;
        }
        atomicMax(&s_thr2_bits, __float_as_int(thr2));
    }
    __syncthreads();
    float R2 = __int_as_float(s_thr2_bits);

    // ---- phase B: classify, compact into shared (cap CAP), overflow slow path ----
    float x[4], y[4], z[4];
    bool nearf[4] = {false, false, false, false};
    int cnt = 0;
    if (inb) {
        x[0] = va.x; y[0] = va.y; z[0] = va.z;
        x[1] = va.w; y[1] = vb.x; z[1] = vb.y;
        x[2] = vb.z; y[2] = vb.w; z[2] = vc.x;
        x[3] = vc.y; y[3] = vc.z; z[3] = vc.w;
        #pragma unroll
        for (int k = 0; k < 4; ++k) {
            float n2 = fmaf(x[k], x[k], fmaf(y[k], y[k], z[k] * z[k]));
            nearf[k] = n2 < R2;
            if (!nearf[k]) out[base + k] = FASTVAL;
            cnt += nearf[k] ? 1 : 0;
        }
    }
    unsigned mask = 0xffffffffu;
    int lane = tid & 31;
    int incl = cnt;
    #pragma unroll
    for (int d = 1; d < 32; d <<= 1) {
        int v = __shfl_up_sync(mask, incl, d);
        if (lane >= d) incl += v;
    }
    int total = __shfl_sync(mask, incl, 31);
    int wbase = 0;
    if (lane == 0) wbase = (total > 0) ? atomicAdd(&s_count, total) : 0;
    wbase = __shfl_sync(mask, wbase, 0);
    int off = wbase + incl - cnt;
    #pragma unroll
    for (int k = 0; k < 4; ++k) {
        if (nearf[k]) {
            if (off < CAP) {
                sbuf[off] = make_float4(x[k], y[k], z[k], __int_as_float(base + k));
            } else {
                // overflow slow path: full scalar loop (correct, rare)
                float ssum = 0.f;
                for (int i = 0; i < N_SPH; ++i) {
                    const float* s = shc + i * 28;
                    float qx = fmaf(s[0], x[k], fmaf(s[2], y[k], fmaf(s[4],  z[k], s[6])));
                    float qy = fmaf(s[8], x[k], fmaf(s[10], y[k], fmaf(s[12], z[k], s[14])));
                    float qz = fmaf(s[16], x[k], fmaf(s[18], y[k], fmaf(s[20], z[k], s[22])));
                    float d2 = fmaf(qx, qx, fmaf(qy, qy, qz * qz));
                    ssum += ex2_ap(fmaf(sqrt_ap(d2), -46.16624130844683f, s[24]));
                }
                out[base + k] = lg2_ap(fmaxf(ssum, 1e-6f)) * -0.021660849392498290f;
            }
            off++;
        }
    }
    __syncthreads();

    // ---- phase C: unit = (pair j, group g of 16 spheres) ----
    // WARP-UNIFORM g (broadcast const loads): j = (u>>8)*32 + (u&31), g = (u>>5)&7
    int count = min(s_count, CAP);
    int pairs = (count + 1) >> 1;
    int total_u = ((pairs + 31) >> 5) << 8;   // pairs rounded to 32, x8 groups

    for (int u = tid; u < total_u; u += 256) {
        int j = ((u >> 8) << 5) | (u & 31);
        int g = (u >> 5) & 7;
        if (j >= pairs) continue;

        int ia = 2 * j;
        int ib = min(2 * j + 1, count - 1);
        float4 A = sbuf[ia];
        float4 B = sbuf[ib];

        u64 X = pk2(A.x, B.x), Y = pk2(A.y, B.y), Z = pk2(A.z, B.z);
        float s0 = 0.f, s1 = 0.f;

        const float* cb = shc + g * (16 * 28);
        #pragma unroll 4
        for (int sp = 0; sp < 16; ++sp) {
            const ulonglong2* C = reinterpret_cast<const ulonglong2*>(cb + sp * 28);
            ulonglong2 m0 = C[0];  // (t00, t01)
            ulonglong2 m1 = C[1];  // (t02, -cx)
            ulonglong2 m2 = C[2];  // (t10, t11)
            ulonglong2 m3 = C[3];  // (t12, -cy)
            ulonglong2 m4 = C[4];  // (t20, t21)
            ulonglong2 m5 = C[5];  // (t22, -cz)
            u64 bb = reinterpret_cast<const u64*>(C)[12];

            u64 qx = f2fma(m0.x, X, f2fma(m0.y, Y, f2fma(m1.x, Z, m1.y)));
            u64 qy = f2fma(m2.x, X, f2fma(m2.y, Y, f2fma(m3.x, Z, m3.y)));
            u64 qz = f2fma(m4.x, X, f2fma(m4.y, Y, f2fma(m5.x, Z, m5.y)));
            u64 d2 = f2fma(qx, qx, f2fma(qy, qy, f2mul(qz, qz)));

            float2 d  = up2(d2);
            float2 bs = up2(bb);
            s0 += ex2_ap(fmaf(sqrt_ap(d.x), -46.16624130844683f, bs.x));
            s1 += ex2_ap(fmaf(sqrt_ap(d.y), -46.16624130844683f, bs.y));
        }

        spart[g * 257 + ia] = s0;
        if (2 * j + 1 < count) spart[g * 257 + ib] = s1;
    }
    __syncthreads();

    // ---- phase D: fixed-order combine of 8 group partials per point ----
    const float NEG_LN2_32 = -0.021660849392498290f;
    for (int pt = tid; pt < count; pt += 256) {
        float acc[8];
        #pragma unroll
        for (int g = 0; g < 8; ++g) acc[g] = spart[g * 257 + pt];
        float s = ((acc[0] + acc[1]) + (acc[2] + acc[3]))
                + ((acc[4] + acc[5]) + (acc[6] + acc[7]));
        out[__float_as_int(sbuf[pt].w)] = lg2_ap(fmaxf(s, 1e-6f)) * NEG_LN2_32;
    }
}

extern "C" void kernel_launch(void* const* d_in, const int* in_sizes, int n_in,
                              void* d_out, int out_size) {
    const float* p       = (const float*)d_in[0];
    const float* centers = (const float*)d_in[1];
    const float* radii   = (const float*)d_in[2];
    const float* tfs     = (const float*)d_in[3];
    float* out = (float*)d_out;

    int npts = in_sizes[0] / 3;
    int blocks = (npts + 1023) / 1024;  // 256 threads x 4 points
    smoothed_fused<<<blocks, 256>>>(p, centers, radii, tfs, out, npts);
}